// round 1
// baseline (speedup 1.0000x reference)
#include <cuda_runtime.h>
#include <cstdint>

// Problem constants (fixed by the reference: B=64, S=2048, D=256, VOCAB=32000)
#define BB 64
#define SS 2048
#define DD 256
#define SPLIT 16
#define SROWS (SS / SPLIT)     // 128 sequence rows per block
#define NBLK (BB * SPLIT)      // 1024 partial blocks

// Scratch for partials: per block, 5 quantities x D floats. ~5.25 MB total.
__device__ float g_part[(size_t)NBLK * 5 * DD];
__device__ float g_wsum[NBLK];

__device__ __forceinline__ float4 f4_add(float4 a, float4 b) {
    return make_float4(a.x + b.x, a.y + b.y, a.z + b.z, a.w + b.w);
}
__device__ __forceinline__ float4 f4_max(float4 a, float4 b) {
    return make_float4(fmaxf(a.x, b.x), fmaxf(a.y, b.y), fmaxf(a.z, b.z), fmaxf(a.w, b.w));
}
__device__ __forceinline__ float4 f4_min(float4 a, float4 b) {
    return make_float4(fminf(a.x, b.x), fminf(a.y, b.y), fminf(a.z, b.z), fminf(a.w, b.w));
}

// ---------------------------------------------------------------------------
// Kernel 1: per-(batch, s-slice) partial reductions.
// Block = 256 threads = 4 subgroups x 64 d-quads (float4 over D=256).
// Each subgroup walks interleaved s-rows; fully-coalesced 128B segments.
// ---------------------------------------------------------------------------
__global__ void __launch_bounds__(256, 6)
partial_kernel(const int* __restrict__ chunk,
               const float4* __restrict__ enc4,   // [B*S, 64] float4 view of [B,S,D]
               const float* __restrict__ idf)
{
    const int bid  = blockIdx.x;
    const int b    = bid >> 4;       // / SPLIT
    const int part = bid & (SPLIT - 1);
    const int t    = threadIdx.x;
    const int q    = t & 63;         // d-quad index (0..63)
    const int sub  = t >> 6;         // subgroup (0..3)

    const float INF = __int_as_float(0x7f800000);
    float4 aw = make_float4(0.f, 0.f, 0.f, 0.f);   // sum w*x
    float4 as = make_float4(0.f, 0.f, 0.f, 0.f);   // sum x
    float4 aq = make_float4(0.f, 0.f, 0.f, 0.f);   // sum x*x
    float4 amx = make_float4(-INF, -INF, -INF, -INF);
    float4 amn = make_float4( INF,  INF,  INF,  INF);
    float wsum = 0.f;

    const int s0 = part * SROWS + sub;
    const int* __restrict__ ch = chunk + b * SS;
    const float4* __restrict__ base = enc4 + (size_t)b * SS * 64 + q;

    #pragma unroll 4
    for (int k = 0; k < SROWS; k += 4) {
        const int s = s0 + k;
        const float w = __ldg(&idf[__ldg(&ch[s])]);
        const float4 v = __ldg(&base[(size_t)s * 64]);
        wsum += w;
        aw.x = fmaf(w, v.x, aw.x); aw.y = fmaf(w, v.y, aw.y);
        aw.z = fmaf(w, v.z, aw.z); aw.w = fmaf(w, v.w, aw.w);
        as = f4_add(as, v);
        aq.x = fmaf(v.x, v.x, aq.x); aq.y = fmaf(v.y, v.y, aq.y);
        aq.z = fmaf(v.z, v.z, aq.z); aq.w = fmaf(v.w, v.w, aq.w);
        amx = f4_max(amx, v);
        amn = f4_min(amn, v);
    }

    // Cross-subgroup combine through shared memory, one quantity at a time.
    __shared__ float4 buf[256];
    __shared__ float  wsh[4];
    float* __restrict__ outp = g_part + (size_t)bid * 5 * DD;

    // quantity 0: weighted sum
    buf[t] = aw; __syncthreads();
    if (sub == 0) {
        float4 r = f4_add(f4_add(buf[q], buf[q + 64]), f4_add(buf[q + 128], buf[q + 192]));
        reinterpret_cast<float4*>(outp + 0 * DD)[q] = r;
    }
    __syncthreads();
    // quantity 1: plain sum
    buf[t] = as; __syncthreads();
    if (sub == 0) {
        float4 r = f4_add(f4_add(buf[q], buf[q + 64]), f4_add(buf[q + 128], buf[q + 192]));
        reinterpret_cast<float4*>(outp + 1 * DD)[q] = r;
    }
    __syncthreads();
    // quantity 2: sum of squares
    buf[t] = aq; __syncthreads();
    if (sub == 0) {
        float4 r = f4_add(f4_add(buf[q], buf[q + 64]), f4_add(buf[q + 128], buf[q + 192]));
        reinterpret_cast<float4*>(outp + 2 * DD)[q] = r;
    }
    __syncthreads();
    // quantity 3: max
    buf[t] = amx;
    if (q == 0) wsh[sub] = wsum;
    __syncthreads();
    if (sub == 0) {
        float4 r = f4_max(f4_max(buf[q], buf[q + 64]), f4_max(buf[q + 128], buf[q + 192]));
        reinterpret_cast<float4*>(outp + 3 * DD)[q] = r;
    }
    __syncthreads();
    // quantity 4: min
    buf[t] = amn; __syncthreads();
    if (sub == 0) {
        float4 r = f4_min(f4_min(buf[q], buf[q + 64]), f4_min(buf[q + 128], buf[q + 192]));
        reinterpret_cast<float4*>(outp + 4 * DD)[q] = r;
    }
    if (t == 0) g_wsum[bid] = wsh[0] + wsh[1] + wsh[2] + wsh[3];
}

// ---------------------------------------------------------------------------
// Kernel 2: combine SPLIT partials per (b, d) and write [B, 4*D] output.
// ---------------------------------------------------------------------------
__global__ void __launch_bounds__(256)
finalize_kernel(float* __restrict__ out)
{
    const int b = blockIdx.x;
    const int d = threadIdx.x;

    const float INF = __int_as_float(0x7f800000);
    float mw = 0.f, sm = 0.f, sq = 0.f, wsum = 0.f;
    float mx = -INF, mn = INF;

    #pragma unroll
    for (int p = 0; p < SPLIT; ++p) {
        const int bid = b * SPLIT + p;
        const float* __restrict__ pp = g_part + (size_t)bid * 5 * DD;
        mw += pp[0 * DD + d];
        sm += pp[1 * DD + d];
        sq += pp[2 * DD + d];
        mx = fmaxf(mx, pp[3 * DD + d]);
        mn = fminf(mn, pp[4 * DD + d]);
        wsum += g_wsum[bid];   // uniform broadcast load
    }

    const float mean_w = mw / wsum;
    float var = (sq - sm * sm * (1.0f / SS)) * (1.0f / (SS - 1));
    var = fmaxf(var, 0.0f);

    float* __restrict__ o = out + (size_t)b * 4 * DD;
    o[0 * DD + d] = mean_w;
    o[1 * DD + d] = mx;
    o[2 * DD + d] = mn;
    o[3 * DD + d] = sqrtf(var);
}

extern "C" void kernel_launch(void* const* d_in, const int* in_sizes, int n_in,
                              void* d_out, int out_size)
{
    const int*   chunk = (const int*)d_in[0];     // [B, S] int32
    const float* enc   = (const float*)d_in[1];   // [B, S, D] float32
    const float* idf   = (const float*)d_in[2];   // [VOCAB] float32
    float* out = (float*)d_out;                   // [B, 4*D] float32

    partial_kernel<<<NBLK, 256>>>(chunk, (const float4*)enc, idf);
    finalize_kernel<<<BB, 256>>>(out);
}

// round 2
// speedup vs baseline: 1.7046x; 1.7046x over previous
#include <cuda_runtime.h>
#include <cstdint>

// Problem constants (fixed by the reference: B=64, S=2048, D=256, VOCAB=32000)
#define BB 64
#define SS 2048
#define DD 256
#define SPLIT 8
#define SROWS (SS / SPLIT)     // 256 sequence rows per block
#define NBLK (BB * SPLIT)      // 512 partial blocks

// Scratch for partials: per block, 5 quantities x D floats. ~2.6 MB total.
__device__ float g_part[(size_t)NBLK * 5 * DD];
__device__ float g_wsum[NBLK];

__device__ __forceinline__ float4 f4_add(float4 a, float4 b) {
    return make_float4(a.x + b.x, a.y + b.y, a.z + b.z, a.w + b.w);
}
__device__ __forceinline__ float4 f4_max(float4 a, float4 b) {
    return make_float4(fmaxf(a.x, b.x), fmaxf(a.y, b.y), fmaxf(a.z, b.z), fmaxf(a.w, b.w));
}
__device__ __forceinline__ float4 f4_min(float4 a, float4 b) {
    return make_float4(fminf(a.x, b.x), fminf(a.y, b.y), fminf(a.z, b.z), fminf(a.w, b.w));
}

// ---------------------------------------------------------------------------
// Kernel 1: per-(batch, s-slice) partial reductions.
// Block = 256 threads = 4 subgroups x 64 d-quads (float4 over D=256).
// Prologue stages the 256 per-row idf weights into shared once; the hot loop
// is then 1 streaming LDG.128 + 1 broadcast LDS per row per thread.
// ---------------------------------------------------------------------------
__global__ void __launch_bounds__(256, 4)
partial_kernel(const int* __restrict__ chunk,
               const float4* __restrict__ enc4,   // [B*S, 64] float4 view of [B,S,D]
               const float* __restrict__ idf)
{
    const int bid  = blockIdx.x;
    const int b    = bid >> 3;           // / SPLIT
    const int part = bid & (SPLIT - 1);
    const int t    = threadIdx.x;
    const int q    = t & 63;             // d-quad index (0..63)
    const int sub  = t >> 6;             // subgroup (0..3)

    __shared__ float wbuf[SROWS];        // per-row weights (1 KB)
    __shared__ float4 buf[256];          // combine buffer (4 KB)
    __shared__ float  wsh[4];

    // Stage weights: one gather per row, done once per CTA.
    {
        const int s = part * SROWS + t;
        wbuf[t] = __ldg(&idf[__ldg(&chunk[b * SS + s])]);
    }
    __syncthreads();

    const float INF = __int_as_float(0x7f800000);
    float4 aw = make_float4(0.f, 0.f, 0.f, 0.f);   // sum w*x
    float4 as = make_float4(0.f, 0.f, 0.f, 0.f);   // sum x
    float4 aq = make_float4(0.f, 0.f, 0.f, 0.f);   // sum x*x
    float4 amx = make_float4(-INF, -INF, -INF, -INF);
    float4 amn = make_float4( INF,  INF,  INF,  INF);

    const float4* __restrict__ base =
        enc4 + (size_t)b * SS * 64 + (size_t)(part * SROWS + sub) * 64 + q;

    #pragma unroll 8
    for (int k = 0; k < SROWS; k += 4) {
        const float  w = wbuf[k + sub];                 // broadcast LDS
        const float4 v = __ldcs(&base[(size_t)k * 64]); // streaming LDG.128
        aw.x = fmaf(w, v.x, aw.x); aw.y = fmaf(w, v.y, aw.y);
        aw.z = fmaf(w, v.z, aw.z); aw.w = fmaf(w, v.w, aw.w);
        as = f4_add(as, v);
        aq.x = fmaf(v.x, v.x, aq.x); aq.y = fmaf(v.y, v.y, aq.y);
        aq.z = fmaf(v.z, v.z, aq.z); aq.w = fmaf(v.w, v.w, aq.w);
        amx = f4_max(amx, v);
        amn = f4_min(amn, v);
    }

    // wsum: warp 0 reduces the staged weights (deterministic tree).
    if (t < 32) {
        float ws = wbuf[t] + wbuf[t + 32] + wbuf[t + 64] + wbuf[t + 96]
                 + wbuf[t + 128] + wbuf[t + 160] + wbuf[t + 192] + wbuf[t + 224];
        #pragma unroll
        for (int off = 16; off > 0; off >>= 1)
            ws += __shfl_down_sync(0xFFFFFFFFu, ws, off);
        if (t == 0) wsh[0] = ws;
    }

    float* __restrict__ outp = g_part + (size_t)bid * 5 * DD;

    // Cross-subgroup combine through shared memory, one quantity at a time.
    buf[t] = aw; __syncthreads();
    if (sub == 0) {
        float4 r = f4_add(f4_add(buf[q], buf[q + 64]), f4_add(buf[q + 128], buf[q + 192]));
        reinterpret_cast<float4*>(outp + 0 * DD)[q] = r;
    }
    __syncthreads();
    buf[t] = as; __syncthreads();
    if (sub == 0) {
        float4 r = f4_add(f4_add(buf[q], buf[q + 64]), f4_add(buf[q + 128], buf[q + 192]));
        reinterpret_cast<float4*>(outp + 1 * DD)[q] = r;
    }
    __syncthreads();
    buf[t] = aq; __syncthreads();
    if (sub == 0) {
        float4 r = f4_add(f4_add(buf[q], buf[q + 64]), f4_add(buf[q + 128], buf[q + 192]));
        reinterpret_cast<float4*>(outp + 2 * DD)[q] = r;
    }
    __syncthreads();
    buf[t] = amx; __syncthreads();
    if (sub == 0) {
        float4 r = f4_max(f4_max(buf[q], buf[q + 64]), f4_max(buf[q + 128], buf[q + 192]));
        reinterpret_cast<float4*>(outp + 3 * DD)[q] = r;
    }
    __syncthreads();
    buf[t] = amn; __syncthreads();
    if (sub == 0) {
        float4 r = f4_min(f4_min(buf[q], buf[q + 64]), f4_min(buf[q + 128], buf[q + 192]));
        reinterpret_cast<float4*>(outp + 4 * DD)[q] = r;
    }
    if (t == 0) g_wsum[bid] = wsh[0];
}

// ---------------------------------------------------------------------------
// Kernel 2: combine SPLIT=8 partials per (b, d) and write [B, 4*D] output.
// 64 CTAs x 256 threads; each thread covers a d-quad for 2 partials (float4,
// 10 independent LDG.128 from L2-hot scratch), then 4-way shared combine.
// ---------------------------------------------------------------------------
__global__ void __launch_bounds__(256)
finalize_kernel(float* __restrict__ out)
{
    const int b   = blockIdx.x;
    const int t   = threadIdx.x;
    const int q   = t & 63;
    const int sub = t >> 6;

    const float INF = __int_as_float(0x7f800000);
    float4 mw = make_float4(0.f, 0.f, 0.f, 0.f);
    float4 sm = make_float4(0.f, 0.f, 0.f, 0.f);
    float4 sq = make_float4(0.f, 0.f, 0.f, 0.f);
    float4 mx = make_float4(-INF, -INF, -INF, -INF);
    float4 mn = make_float4( INF,  INF,  INF,  INF);
    float ws = 0.f;

    #pragma unroll
    for (int j = 0; j < 2; ++j) {
        const int p = sub * 2 + j;
        const int bid = b * SPLIT + p;
        const float4* __restrict__ pp =
            reinterpret_cast<const float4*>(g_part + (size_t)bid * 5 * DD);
        mw = f4_add(mw, pp[0 * 64 + q]);
        sm = f4_add(sm, pp[1 * 64 + q]);
        sq = f4_add(sq, pp[2 * 64 + q]);
        mx = f4_max(mx, pp[3 * 64 + q]);
        mn = f4_min(mn, pp[4 * 64 + q]);
        ws += g_wsum[bid];
    }

    __shared__ float4 buf[256];
    __shared__ float  wsh[4];
    if (q == 0) wsh[sub] = ws;

    float4 rw, rs, rq, rx, rn;
    buf[t] = mw; __syncthreads();
    if (sub == 0) rw = f4_add(f4_add(buf[q], buf[q + 64]), f4_add(buf[q + 128], buf[q + 192]));
    __syncthreads();
    buf[t] = sm; __syncthreads();
    if (sub == 0) rs = f4_add(f4_add(buf[q], buf[q + 64]), f4_add(buf[q + 128], buf[q + 192]));
    __syncthreads();
    buf[t] = sq; __syncthreads();
    if (sub == 0) rq = f4_add(f4_add(buf[q], buf[q + 64]), f4_add(buf[q + 128], buf[q + 192]));
    __syncthreads();
    buf[t] = mx; __syncthreads();
    if (sub == 0) rx = f4_max(f4_max(buf[q], buf[q + 64]), f4_max(buf[q + 128], buf[q + 192]));
    __syncthreads();
    buf[t] = mn; __syncthreads();
    if (sub == 0) {
        rn = f4_min(f4_min(buf[q], buf[q + 64]), f4_min(buf[q + 128], buf[q + 192]));

        const float wsum = wsh[0] + wsh[1] + wsh[2] + wsh[3];
        const float inv_w = 1.0f / wsum;
        const float inv_s = 1.0f / (float)SS;
        const float inv_n1 = 1.0f / (float)(SS - 1);

        float4 mean = make_float4(rw.x * inv_w, rw.y * inv_w, rw.z * inv_w, rw.w * inv_w);
        float4 var;
        var.x = fmaxf((rq.x - rs.x * rs.x * inv_s) * inv_n1, 0.f);
        var.y = fmaxf((rq.y - rs.y * rs.y * inv_s) * inv_n1, 0.f);
        var.z = fmaxf((rq.z - rs.z * rs.z * inv_s) * inv_n1, 0.f);
        var.w = fmaxf((rq.w - rs.w * rs.w * inv_s) * inv_n1, 0.f);
        float4 sd = make_float4(sqrtf(var.x), sqrtf(var.y), sqrtf(var.z), sqrtf(var.w));

        float4* __restrict__ o = reinterpret_cast<float4*>(out + (size_t)b * 4 * DD);
        o[0 * 64 + q] = mean;
        o[1 * 64 + q] = rx;
        o[2 * 64 + q] = rn;
        o[3 * 64 + q] = sd;
    }
}

extern "C" void kernel_launch(void* const* d_in, const int* in_sizes, int n_in,
                              void* d_out, int out_size)
{
    const int*   chunk = (const int*)d_in[0];     // [B, S] int32
    const float* enc   = (const float*)d_in[1];   // [B, S, D] float32
    const float* idf   = (const float*)d_in[2];   // [VOCAB] float32
    float* out = (float*)d_out;                   // [B, 4*D] float32

    partial_kernel<<<NBLK, 256>>>(chunk, (const float4*)enc, idf);
    finalize_kernel<<<BB, 256>>>(out);
}

// round 3
// speedup vs baseline: 1.7565x; 1.0304x over previous
#include <cuda_runtime.h>
#include <cstdint>

// Problem constants (fixed by the reference: B=64, S=2048, D=256, VOCAB=32000)
#define BB 64
#define SS 2048
#define DD 256
#define SPLIT 8
#define SROWS (SS / SPLIT)     // 256 sequence rows per block
#define NBLK (BB * SPLIT)      // 512 partial blocks

// Scratch for partials: per block, 5 quantities x D floats. ~2.6 MB total.
__device__ float g_part[(size_t)NBLK * 5 * DD];
__device__ float g_wsum[NBLK];
__device__ unsigned int g_cnt[BB];   // zero-initialized; reset to 0 by finalizer

__device__ __forceinline__ float4 f4_add(float4 a, float4 b) {
    return make_float4(a.x + b.x, a.y + b.y, a.z + b.z, a.w + b.w);
}
__device__ __forceinline__ float4 f4_max(float4 a, float4 b) {
    return make_float4(fmaxf(a.x, b.x), fmaxf(a.y, b.y), fmaxf(a.z, b.z), fmaxf(a.w, b.w));
}
__device__ __forceinline__ float4 f4_min(float4 a, float4 b) {
    return make_float4(fminf(a.x, b.x), fminf(a.y, b.y), fminf(a.z, b.z), fminf(a.w, b.w));
}

// ---------------------------------------------------------------------------
// Fused kernel: per-(batch, s-slice) partial reductions + last-CTA finalize.
// Block = 256 threads = 4 subgroups x 64 d-quads (float4 over D=256).
// Prologue stages 256 per-row idf weights into shared; the hot loop is
// 1 streaming LDG.128 + 1 broadcast LDS per row per thread. The 8th CTA to
// finish for a batch combines the 8 L2-hot partials and writes the output.
// ---------------------------------------------------------------------------
__global__ void __launch_bounds__(256, 4)
fused_kernel(const int* __restrict__ chunk,
             const float4* __restrict__ enc4,   // [B*S, 64] float4 view of [B,S,D]
             const float* __restrict__ idf,
             float* __restrict__ out)           // [B, 4*D]
{
    const int bid  = blockIdx.x;
    const int b    = bid >> 3;           // / SPLIT
    const int part = bid & (SPLIT - 1);
    const int t    = threadIdx.x;
    const int q    = t & 63;             // d-quad index (0..63)
    const int sub  = t >> 6;             // subgroup (0..3)

    __shared__ float wbuf[SROWS];        // per-row weights (1 KB)
    __shared__ float4 buf[256];          // combine buffer (4 KB)
    __shared__ float  wsh[4];
    __shared__ int    is_last;

    // Stage weights: one gather per row, done once per CTA.
    {
        const int s = part * SROWS + t;
        wbuf[t] = __ldg(&idf[__ldg(&chunk[b * SS + s])]);
    }
    __syncthreads();

    const float INF = __int_as_float(0x7f800000);
    float4 aw = make_float4(0.f, 0.f, 0.f, 0.f);   // sum w*x
    float4 as = make_float4(0.f, 0.f, 0.f, 0.f);   // sum x
    float4 aq = make_float4(0.f, 0.f, 0.f, 0.f);   // sum x*x
    float4 amx = make_float4(-INF, -INF, -INF, -INF);
    float4 amn = make_float4( INF,  INF,  INF,  INF);

    const float4* __restrict__ base =
        enc4 + (size_t)b * SS * 64 + (size_t)(part * SROWS + sub) * 64 + q;

    #pragma unroll 8
    for (int k = 0; k < SROWS; k += 4) {
        const float  w = wbuf[k + sub];                 // broadcast LDS
        const float4 v = __ldcs(&base[(size_t)k * 64]); // streaming LDG.128
        aw.x = fmaf(w, v.x, aw.x); aw.y = fmaf(w, v.y, aw.y);
        aw.z = fmaf(w, v.z, aw.z); aw.w = fmaf(w, v.w, aw.w);
        as = f4_add(as, v);
        aq.x = fmaf(v.x, v.x, aq.x); aq.y = fmaf(v.y, v.y, aq.y);
        aq.z = fmaf(v.z, v.z, aq.z); aq.w = fmaf(v.w, v.w, aq.w);
        amx = f4_max(amx, v);
        amn = f4_min(amn, v);
    }

    // wsum: warp 0 reduces the staged weights (deterministic tree).
    if (t < 32) {
        float ws = wbuf[t] + wbuf[t + 32] + wbuf[t + 64] + wbuf[t + 96]
                 + wbuf[t + 128] + wbuf[t + 160] + wbuf[t + 192] + wbuf[t + 224];
        #pragma unroll
        for (int off = 16; off > 0; off >>= 1)
            ws += __shfl_down_sync(0xFFFFFFFFu, ws, off);
        if (t == 0) wsh[0] = ws;
    }

    float* __restrict__ outp = g_part + (size_t)bid * 5 * DD;

    // Cross-subgroup combine through shared memory, one quantity at a time.
    buf[t] = aw; __syncthreads();
    if (sub == 0) {
        float4 r = f4_add(f4_add(buf[q], buf[q + 64]), f4_add(buf[q + 128], buf[q + 192]));
        reinterpret_cast<float4*>(outp + 0 * DD)[q] = r;
    }
    __syncthreads();
    buf[t] = as; __syncthreads();
    if (sub == 0) {
        float4 r = f4_add(f4_add(buf[q], buf[q + 64]), f4_add(buf[q + 128], buf[q + 192]));
        reinterpret_cast<float4*>(outp + 1 * DD)[q] = r;
    }
    __syncthreads();
    buf[t] = aq; __syncthreads();
    if (sub == 0) {
        float4 r = f4_add(f4_add(buf[q], buf[q + 64]), f4_add(buf[q + 128], buf[q + 192]));
        reinterpret_cast<float4*>(outp + 2 * DD)[q] = r;
    }
    __syncthreads();
    buf[t] = amx; __syncthreads();
    if (sub == 0) {
        float4 r = f4_max(f4_max(buf[q], buf[q + 64]), f4_max(buf[q + 128], buf[q + 192]));
        reinterpret_cast<float4*>(outp + 3 * DD)[q] = r;
    }
    __syncthreads();
    buf[t] = amn; __syncthreads();
    if (sub == 0) {
        float4 r = f4_min(f4_min(buf[q], buf[q + 64]), f4_min(buf[q + 128], buf[q + 192]));
        reinterpret_cast<float4*>(outp + 4 * DD)[q] = r;
        if (q == 0) g_wsum[bid] = wsh[0];
        __threadfence();   // release this CTA's partials (writers fence)
    }
    __syncthreads();

    // Last CTA of this batch finalizes.
    if (t == 0) {
        unsigned int old = atomicAdd(&g_cnt[b], 1u);
        is_last = (old == SPLIT - 1);
    }
    __syncthreads();
    if (!is_last) return;
    if (t == 0) {
        __threadfence();           // acquire side
        g_cnt[b] = 0;              // reset for next graph replay
    }
    __syncthreads();

    // ---- Finalize batch b: combine SPLIT=8 partials (L2-hot, ~40 KB) ----
    float4 mw = make_float4(0.f, 0.f, 0.f, 0.f);
    float4 sm = make_float4(0.f, 0.f, 0.f, 0.f);
    float4 sq = make_float4(0.f, 0.f, 0.f, 0.f);
    float4 mx = make_float4(-INF, -INF, -INF, -INF);
    float4 mn = make_float4( INF,  INF,  INF,  INF);
    float ws = 0.f;

    #pragma unroll
    for (int j = 0; j < 2; ++j) {
        const int p = sub * 2 + j;
        const int pbid = b * SPLIT + p;
        const float4* __restrict__ pp =
            reinterpret_cast<const float4*>(g_part + (size_t)pbid * 5 * DD);
        mw = f4_add(mw, __ldcg(&pp[0 * 64 + q]));
        sm = f4_add(sm, __ldcg(&pp[1 * 64 + q]));
        sq = f4_add(sq, __ldcg(&pp[2 * 64 + q]));
        mx = f4_max(mx, __ldcg(&pp[3 * 64 + q]));
        mn = f4_min(mn, __ldcg(&pp[4 * 64 + q]));
        ws += __ldcg(&g_wsum[pbid]);
    }

    if (q == 0) wsh[sub] = ws;

    float4 rw, rs, rq, rx, rn;
    buf[t] = mw; __syncthreads();
    if (sub == 0) rw = f4_add(f4_add(buf[q], buf[q + 64]), f4_add(buf[q + 128], buf[q + 192]));
    __syncthreads();
    buf[t] = sm; __syncthreads();
    if (sub == 0) rs = f4_add(f4_add(buf[q], buf[q + 64]), f4_add(buf[q + 128], buf[q + 192]));
    __syncthreads();
    buf[t] = sq; __syncthreads();
    if (sub == 0) rq = f4_add(f4_add(buf[q], buf[q + 64]), f4_add(buf[q + 128], buf[q + 192]));
    __syncthreads();
    buf[t] = mx; __syncthreads();
    if (sub == 0) rx = f4_max(f4_max(buf[q], buf[q + 64]), f4_max(buf[q + 128], buf[q + 192]));
    __syncthreads();
    buf[t] = mn; __syncthreads();
    if (sub == 0) {
        rn = f4_min(f4_min(buf[q], buf[q + 64]), f4_min(buf[q + 128], buf[q + 192]));

        const float wsum = wsh[0] + wsh[1] + wsh[2] + wsh[3];
        const float inv_w = 1.0f / wsum;
        const float inv_s = 1.0f / (float)SS;
        const float inv_n1 = 1.0f / (float)(SS - 1);

        float4 mean = make_float4(rw.x * inv_w, rw.y * inv_w, rw.z * inv_w, rw.w * inv_w);
        float4 var;
        var.x = fmaxf((rq.x - rs.x * rs.x * inv_s) * inv_n1, 0.f);
        var.y = fmaxf((rq.y - rs.y * rs.y * inv_s) * inv_n1, 0.f);
        var.z = fmaxf((rq.z - rs.z * rs.z * inv_s) * inv_n1, 0.f);
        var.w = fmaxf((rq.w - rs.w * rs.w * inv_s) * inv_n1, 0.f);
        float4 sd = make_float4(sqrtf(var.x), sqrtf(var.y), sqrtf(var.z), sqrtf(var.w));

        float4* __restrict__ o = reinterpret_cast<float4*>(out + (size_t)b * 4 * DD);
        o[0 * 64 + q] = mean;
        o[1 * 64 + q] = rx;
        o[2 * 64 + q] = rn;
        o[3 * 64 + q] = sd;
    }
}

extern "C" void kernel_launch(void* const* d_in, const int* in_sizes, int n_in,
                              void* d_out, int out_size)
{
    const int*   chunk = (const int*)d_in[0];     // [B, S] int32
    const float* enc   = (const float*)d_in[1];   // [B, S, D] float32
    const float* idf   = (const float*)d_in[2];   // [VOCAB] float32
    float* out = (float*)d_out;                   // [B, 4*D] float32

    fused_kernel<<<NBLK, 256>>>(chunk, (const float4*)enc, idf, out);
}